// round 1
// baseline (speedup 1.0000x reference)
#include <cuda_runtime.h>
#include <math.h>

#define BATCH  4
#define SEQ    2048
#define HEADS  8
#define DEPTH  64
#define DMODEL 512
#define MROWS  (BATCH*SEQ)   // 8192

// Scratch (allocation-free rule: __device__ globals)
__device__ float g_Q[MROWS * DMODEL];
__device__ float g_K[MROWS * DMODEL];
__device__ float g_V[MROWS * DMODEL];
__device__ float g_A[MROWS * DMODEL];

// ---------------------------------------------------------------------------
// GEMM: out[m][n] = sum_k A[m][k] * W[n][k]     (y = x @ W^T)
// A: [M x 512], W: [512 x 512] row-major. Tile 64x64, BK=16, 256 thr, 4x4/thr.
// ---------------------------------------------------------------------------
__global__ __launch_bounds__(256) void gemm_xwt_kernel(
    const float* __restrict__ A, const float* __restrict__ W,
    float* __restrict__ out)
{
    __shared__ float As[16 * 68];   // As[k][m], padded row 68
    __shared__ float Bs[16 * 68];   // Bs[k][n]

    const int tx = threadIdx.x, ty = threadIdx.y;
    const int tid = ty * 16 + tx;
    const int m0 = blockIdx.y * 64, n0 = blockIdx.x * 64;

    // loader: row = tid/4 (0..63), k-quad = (tid&3)*4  -> fully coalesced
    const int lrow = tid >> 2;
    const int lk   = (tid & 3) << 2;

    const float* Aptr = A + (size_t)(m0 + lrow) * DMODEL + lk;
    const float* Wptr = W + (size_t)(n0 + lrow) * DMODEL + lk;

    float acc[4][4] = {};

    for (int k0 = 0; k0 < DMODEL; k0 += 16) {
        float4 av = *(const float4*)(Aptr + k0);
        float4 bv = *(const float4*)(Wptr + k0);
        As[(lk + 0) * 68 + lrow] = av.x;
        As[(lk + 1) * 68 + lrow] = av.y;
        As[(lk + 2) * 68 + lrow] = av.z;
        As[(lk + 3) * 68 + lrow] = av.w;
        Bs[(lk + 0) * 68 + lrow] = bv.x;
        Bs[(lk + 1) * 68 + lrow] = bv.y;
        Bs[(lk + 2) * 68 + lrow] = bv.z;
        Bs[(lk + 3) * 68 + lrow] = bv.w;
        __syncthreads();

        #pragma unroll
        for (int kk = 0; kk < 16; kk++) {
            float4 a = *(const float4*)(As + kk * 68 + (ty << 2));
            float4 b = *(const float4*)(Bs + kk * 68 + (tx << 2));
            acc[0][0] += a.x * b.x; acc[0][1] += a.x * b.y; acc[0][2] += a.x * b.z; acc[0][3] += a.x * b.w;
            acc[1][0] += a.y * b.x; acc[1][1] += a.y * b.y; acc[1][2] += a.y * b.z; acc[1][3] += a.y * b.w;
            acc[2][0] += a.z * b.x; acc[2][1] += a.z * b.y; acc[2][2] += a.z * b.z; acc[2][3] += a.z * b.w;
            acc[3][0] += a.w * b.x; acc[3][1] += a.w * b.y; acc[3][2] += a.w * b.z; acc[3][3] += a.w * b.w;
        }
        __syncthreads();
    }

    float* O = out + (size_t)(m0 + (ty << 2)) * DMODEL + n0 + (tx << 2);
    #pragma unroll
    for (int i = 0; i < 4; i++) {
        float4 v = make_float4(acc[i][0], acc[i][1], acc[i][2], acc[i][3]);
        *(float4*)(O + (size_t)i * DMODEL) = v;
    }
}

// ---------------------------------------------------------------------------
// Attention: per CTA one (b, h, 64-query tile). Streams over 32 K/V tiles.
// S = Q K^T * 1/8,  P = sigmoid(S - log(SEQ)),  O += P V   (no renorm needed)
// Q/K kept in smem transposed [d][r] with XOR swizzle on float4 groups
// (conflict-free transpose stores AND conflict-free LDS.128 inner reads).
// Smem = 3 * 64*64*4 = 48 KB exactly (static).
// ---------------------------------------------------------------------------
__global__ __launch_bounds__(256) void attn_kernel(
    const float* __restrict__ Q, const float* __restrict__ K,
    const float* __restrict__ V, float* __restrict__ O)
{
    __shared__ float Qt[64 * 64];   // Qt[d][swz(r)]
    __shared__ float KVt[64 * 64];  // K transposed (swz) / V row-major (reused)
    __shared__ float Ps[64 * 64];   // P row-major

    const int tx = threadIdx.x, ty = threadIdx.y;
    const int tid = ty * 16 + tx;
    const int b = blockIdx.z, h = blockIdx.y, q0 = blockIdx.x * 64;

    const int lr  = tid & 15;   // row within 16-group (transpose loads)
    const int ld4 = tid >> 4;   // float4 column index 0..15

    const float bias  = -logf((float)SEQ);
    const float scale = 0.125f;  // 1/sqrt(64)

    // ---- load Q tile transposed+swizzled: logical (d, r) -> Qt[d*64 + phys]
    {
        const float* Qb = Q + ((size_t)(b * SEQ + q0) * DMODEL) + h * DEPTH + (ld4 << 2);
        #pragma unroll
        for (int rr = 0; rr < 4; rr++) {
            int r = lr + 16 * rr;
            float4 v = *(const float4*)(Qb + (size_t)r * DMODEL);
            float vv[4] = {v.x, v.y, v.z, v.w};
            #pragma unroll
            for (int z = 0; z < 4; z++) {
                int d = (ld4 << 2) + z;
                int phys = ((((r >> 2) ^ (d & 15)) << 2) | (r & 3));
                Qt[d * 64 + phys] = vv[z];
            }
        }
    }

    float o[4][4] = {};

    for (int kt = 0; kt < SEQ / 64; kt++) {
        __syncthreads();  // prev PV done (and Qt ready on iter 0)

        // ---- load K tile transposed+swizzled into KVt
        {
            const float* Kb = K + ((size_t)(b * SEQ + kt * 64) * DMODEL) + h * DEPTH + (ld4 << 2);
            #pragma unroll
            for (int rr = 0; rr < 4; rr++) {
                int r = lr + 16 * rr;
                float4 v = *(const float4*)(Kb + (size_t)r * DMODEL);
                float vv[4] = {v.x, v.y, v.z, v.w};
                #pragma unroll
                for (int z = 0; z < 4; z++) {
                    int d = (ld4 << 2) + z;
                    int phys = ((((r >> 2) ^ (d & 15)) << 2) | (r & 3));
                    KVt[d * 64 + phys] = vv[z];
                }
            }
        }
        __syncthreads();

        // ---- S = Q K^T  (4x4 per thread, contraction over d)
        float s[4][4] = {};
        #pragma unroll 8
        for (int d = 0; d < 64; d++) {
            int sw = d & 15;
            float4 a  = *(const float4*)(Qt  + d * 64 + ((ty ^ sw) << 2));
            float4 bv = *(const float4*)(KVt + d * 64 + ((tx ^ sw) << 2));
            s[0][0] += a.x * bv.x; s[0][1] += a.x * bv.y; s[0][2] += a.x * bv.z; s[0][3] += a.x * bv.w;
            s[1][0] += a.y * bv.x; s[1][1] += a.y * bv.y; s[1][2] += a.y * bv.z; s[1][3] += a.y * bv.w;
            s[2][0] += a.z * bv.x; s[2][1] += a.z * bv.y; s[2][2] += a.z * bv.z; s[2][3] += a.z * bv.w;
            s[3][0] += a.w * bv.x; s[3][1] += a.w * bv.y; s[3][2] += a.w * bv.z; s[3][3] += a.w * bv.w;
        }

        // ---- P = sigmoid(S*scale + bias) -> smem (row-major)
        #pragma unroll
        for (int i = 0; i < 4; i++) {
            float4 p;
            p.x = 1.f / (1.f + __expf(-(s[i][0] * scale + bias)));
            p.y = 1.f / (1.f + __expf(-(s[i][1] * scale + bias)));
            p.z = 1.f / (1.f + __expf(-(s[i][2] * scale + bias)));
            p.w = 1.f / (1.f + __expf(-(s[i][3] * scale + bias)));
            *(float4*)(Ps + (size_t)(((ty << 2) + i) * 64) + (tx << 2)) = p;
        }
        __syncthreads();  // Ps visible, KVt free

        // ---- load V tile row-major into KVt: KVt[c][dd]
        {
            const float* Vb = V + ((size_t)(b * SEQ + kt * 64) * DMODEL) + h * DEPTH;
            #pragma unroll
            for (int rr = 0; rr < 4; rr++) {
                int c = ld4 + 16 * rr;
                float4 v = *(const float4*)(Vb + (size_t)c * DMODEL + (lr << 2));
                *(float4*)(KVt + c * 64 + (lr << 2)) = v;
            }
        }
        __syncthreads();

        // ---- O += P V  (contraction over c)
        #pragma unroll 8
        for (int c = 0; c < 64; c++) {
            float a0 = Ps[((ty << 2) + 0) * 64 + c];
            float a1 = Ps[((ty << 2) + 1) * 64 + c];
            float a2 = Ps[((ty << 2) + 2) * 64 + c];
            float a3 = Ps[((ty << 2) + 3) * 64 + c];
            float4 bv = *(const float4*)(KVt + c * 64 + (tx << 2));
            o[0][0] += a0 * bv.x; o[0][1] += a0 * bv.y; o[0][2] += a0 * bv.z; o[0][3] += a0 * bv.w;
            o[1][0] += a1 * bv.x; o[1][1] += a1 * bv.y; o[1][2] += a1 * bv.z; o[1][3] += a1 * bv.w;
            o[2][0] += a2 * bv.x; o[2][1] += a2 * bv.y; o[2][2] += a2 * bv.z; o[2][3] += a2 * bv.w;
            o[3][0] += a3 * bv.x; o[3][1] += a3 * bv.y; o[3][2] += a3 * bv.z; o[3][3] += a3 * bv.w;
        }
    }

    // ---- write O tile to merged [b, s, h*D] layout
    float* Ob = O + ((size_t)(b * SEQ + q0 + (ty << 2)) * DMODEL) + h * DEPTH + (tx << 2);
    #pragma unroll
    for (int i = 0; i < 4; i++) {
        float4 v = make_float4(o[i][0], o[i][1], o[i][2], o[i][3]);
        *(float4*)(Ob + (size_t)i * DMODEL) = v;
    }
}

// ---------------------------------------------------------------------------
extern "C" void kernel_launch(void* const* d_in, const int* in_sizes, int n_in,
                              void* d_out, int out_size) {
    const float* x  = (const float*)d_in[0];
    const float* Wq = (const float*)d_in[1];
    const float* Wk = (const float*)d_in[2];
    const float* Wv = (const float*)d_in[3];
    const float* Wo = (const float*)d_in[4];
    float* out = (float*)d_out;

    float *Qp, *Kp, *Vp, *Ap;
    cudaGetSymbolAddress((void**)&Qp, g_Q);
    cudaGetSymbolAddress((void**)&Kp, g_K);
    cudaGetSymbolAddress((void**)&Vp, g_V);
    cudaGetSymbolAddress((void**)&Ap, g_A);

    dim3 tb(16, 16);
    dim3 gg(DMODEL / 64, MROWS / 64);          // (8, 128)
    dim3 ga(SEQ / 64, HEADS, BATCH);           // (32, 8, 4)

    gemm_xwt_kernel<<<gg, tb>>>(x, Wq, Qp);
    gemm_xwt_kernel<<<gg, tb>>>(x, Wk, Kp);
    gemm_xwt_kernel<<<gg, tb>>>(x, Wv, Vp);
    attn_kernel<<<ga, tb>>>(Qp, Kp, Vp, Ap);
    gemm_xwt_kernel<<<gg, tb>>>(Ap, Wo, out);
}

// round 2
// speedup vs baseline: 1.0029x; 1.0029x over previous
#include <cuda_runtime.h>
#include <math.h>

#define BATCH  4
#define SEQ    2048
#define HEADS  8
#define DEPTH  64
#define DMODEL 512
#define MROWS  (BATCH*SEQ)   // 8192

// Scratch (allocation-free rule: __device__ globals)
__device__ float g_Q[MROWS * DMODEL];
__device__ float g_K[MROWS * DMODEL];
__device__ float g_V[MROWS * DMODEL];
__device__ float g_A[MROWS * DMODEL];

// ---------------------------------------------------------------------------
// GEMM: out[m][n] = sum_k A[m][k] * W[n][k]     (y = x @ W^T)
// A: [M x 512], W: [512 x 512] row-major. Tile 64x64, BK=16, 256 thr, 4x4/thr.
// ---------------------------------------------------------------------------
__global__ __launch_bounds__(256) void gemm_xwt_kernel(
    const float* __restrict__ A, const float* __restrict__ W,
    float* __restrict__ out)
{
    __shared__ float As[16 * 68];   // As[k][m], padded row 68
    __shared__ float Bs[16 * 68];   // Bs[k][n]

    const int tx = threadIdx.x, ty = threadIdx.y;
    const int tid = ty * 16 + tx;
    const int m0 = blockIdx.y * 64, n0 = blockIdx.x * 64;

    // loader: row = tid/4 (0..63), k-quad = (tid&3)*4  -> fully coalesced
    const int lrow = tid >> 2;
    const int lk   = (tid & 3) << 2;

    const float* Aptr = A + (size_t)(m0 + lrow) * DMODEL + lk;
    const float* Wptr = W + (size_t)(n0 + lrow) * DMODEL + lk;

    float acc[4][4] = {};

    for (int k0 = 0; k0 < DMODEL; k0 += 16) {
        float4 av = *(const float4*)(Aptr + k0);
        float4 bv = *(const float4*)(Wptr + k0);
        As[(lk + 0) * 68 + lrow] = av.x;
        As[(lk + 1) * 68 + lrow] = av.y;
        As[(lk + 2) * 68 + lrow] = av.z;
        As[(lk + 3) * 68 + lrow] = av.w;
        Bs[(lk + 0) * 68 + lrow] = bv.x;
        Bs[(lk + 1) * 68 + lrow] = bv.y;
        Bs[(lk + 2) * 68 + lrow] = bv.z;
        Bs[(lk + 3) * 68 + lrow] = bv.w;
        __syncthreads();

        #pragma unroll
        for (int kk = 0; kk < 16; kk++) {
            float4 a = *(const float4*)(As + kk * 68 + (ty << 2));
            float4 b = *(const float4*)(Bs + kk * 68 + (tx << 2));
            acc[0][0] += a.x * b.x; acc[0][1] += a.x * b.y; acc[0][2] += a.x * b.z; acc[0][3] += a.x * b.w;
            acc[1][0] += a.y * b.x; acc[1][1] += a.y * b.y; acc[1][2] += a.y * b.z; acc[1][3] += a.y * b.w;
            acc[2][0] += a.z * b.x; acc[2][1] += a.z * b.y; acc[2][2] += a.z * b.z; acc[2][3] += a.z * b.w;
            acc[3][0] += a.w * b.x; acc[3][1] += a.w * b.y; acc[3][2] += a.w * b.z; acc[3][3] += a.w * b.w;
        }
        __syncthreads();
    }

    float* O = out + (size_t)(m0 + (ty << 2)) * DMODEL + n0 + (tx << 2);
    #pragma unroll
    for (int i = 0; i < 4; i++) {
        float4 v = make_float4(acc[i][0], acc[i][1], acc[i][2], acc[i][3]);
        *(float4*)(O + (size_t)i * DMODEL) = v;
    }
}

// ---------------------------------------------------------------------------
// Attention: per CTA one (b, h, 64-query tile). Streams over 32 K/V tiles.
// S = Q K^T * 1/8,  P = sigmoid(S - log(SEQ)),  O += P V   (no renorm needed)
// Q/K kept in smem transposed [d][r] with XOR swizzle on float4 groups
// (conflict-free transpose stores AND conflict-free LDS.128 inner reads).
// Smem = 3 * 64*64*4 = 48 KB exactly (static).
// ---------------------------------------------------------------------------
__global__ __launch_bounds__(256) void attn_kernel(
    const float* __restrict__ Q, const float* __restrict__ K,
    const float* __restrict__ V, float* __restrict__ O)
{
    __shared__ float Qt[64 * 64];   // Qt[d][swz(r)]
    __shared__ float KVt[64 * 64];  // K transposed (swz) / V row-major (reused)
    __shared__ float Ps[64 * 64];   // P row-major

    const int tx = threadIdx.x, ty = threadIdx.y;
    const int tid = ty * 16 + tx;
    const int b = blockIdx.z, h = blockIdx.y, q0 = blockIdx.x * 64;

    const int lr  = tid & 15;   // row within 16-group (transpose loads)
    const int ld4 = tid >> 4;   // float4 column index 0..15

    const float bias  = -logf((float)SEQ);
    const float scale = 0.125f;  // 1/sqrt(64)

    // ---- load Q tile transposed+swizzled: logical (d, r) -> Qt[d*64 + phys]
    {
        const float* Qb = Q + ((size_t)(b * SEQ + q0) * DMODEL) + h * DEPTH + (ld4 << 2);
        #pragma unroll
        for (int rr = 0; rr < 4; rr++) {
            int r = lr + 16 * rr;
            float4 v = *(const float4*)(Qb + (size_t)r * DMODEL);
            float vv[4] = {v.x, v.y, v.z, v.w};
            #pragma unroll
            for (int z = 0; z < 4; z++) {
                int d = (ld4 << 2) + z;
                int phys = ((((r >> 2) ^ (d & 15)) << 2) | (r & 3));
                Qt[d * 64 + phys] = vv[z];
            }
        }
    }

    float o[4][4] = {};

    for (int kt = 0; kt < SEQ / 64; kt++) {
        __syncthreads();  // prev PV done (and Qt ready on iter 0)

        // ---- load K tile transposed+swizzled into KVt
        {
            const float* Kb = K + ((size_t)(b * SEQ + kt * 64) * DMODEL) + h * DEPTH + (ld4 << 2);
            #pragma unroll
            for (int rr = 0; rr < 4; rr++) {
                int r = lr + 16 * rr;
                float4 v = *(const float4*)(Kb + (size_t)r * DMODEL);
                float vv[4] = {v.x, v.y, v.z, v.w};
                #pragma unroll
                for (int z = 0; z < 4; z++) {
                    int d = (ld4 << 2) + z;
                    int phys = ((((r >> 2) ^ (d & 15)) << 2) | (r & 3));
                    KVt[d * 64 + phys] = vv[z];
                }
            }
        }
        __syncthreads();

        // ---- S = Q K^T  (4x4 per thread, contraction over d)
        float s[4][4] = {};
        #pragma unroll 8
        for (int d = 0; d < 64; d++) {
            int sw = d & 15;
            float4 a  = *(const float4*)(Qt  + d * 64 + ((ty ^ sw) << 2));
            float4 bv = *(const float4*)(KVt + d * 64 + ((tx ^ sw) << 2));
            s[0][0] += a.x * bv.x; s[0][1] += a.x * bv.y; s[0][2] += a.x * bv.z; s[0][3] += a.x * bv.w;
            s[1][0] += a.y * bv.x; s[1][1] += a.y * bv.y; s[1][2] += a.y * bv.z; s[1][3] += a.y * bv.w;
            s[2][0] += a.z * bv.x; s[2][1] += a.z * bv.y; s[2][2] += a.z * bv.z; s[2][3] += a.z * bv.w;
            s[3][0] += a.w * bv.x; s[3][1] += a.w * bv.y; s[3][2] += a.w * bv.z; s[3][3] += a.w * bv.w;
        }

        // ---- P = sigmoid(S*scale + bias) -> smem (row-major)
        #pragma unroll
        for (int i = 0; i < 4; i++) {
            float4 p;
            p.x = 1.f / (1.f + __expf(-(s[i][0] * scale + bias)));
            p.y = 1.f / (1.f + __expf(-(s[i][1] * scale + bias)));
            p.z = 1.f / (1.f + __expf(-(s[i][2] * scale + bias)));
            p.w = 1.f / (1.f + __expf(-(s[i][3] * scale + bias)));
            *(float4*)(Ps + (size_t)(((ty << 2) + i) * 64) + (tx << 2)) = p;
        }
        __syncthreads();  // Ps visible, KVt free

        // ---- load V tile row-major into KVt: KVt[c][dd]
        {
            const float* Vb = V + ((size_t)(b * SEQ + kt * 64) * DMODEL) + h * DEPTH;
            #pragma unroll
            for (int rr = 0; rr < 4; rr++) {
                int c = ld4 + 16 * rr;
                float4 v = *(const float4*)(Vb + (size_t)c * DMODEL + (lr << 2));
                *(float4*)(KVt + c * 64 + (lr << 2)) = v;
            }
        }
        __syncthreads();

        // ---- O += P V  (contraction over c)
        #pragma unroll 8
        for (int c = 0; c < 64; c++) {
            float a0 = Ps[((ty << 2) + 0) * 64 + c];
            float a1 = Ps[((ty << 2) + 1) * 64 + c];
            float a2 = Ps[((ty << 2) + 2) * 64 + c];
            float a3 = Ps[((ty << 2) + 3) * 64 + c];
            float4 bv = *(const float4*)(KVt + c * 64 + (tx << 2));
            o[0][0] += a0 * bv.x; o[0][1] += a0 * bv.y; o[0][2] += a0 * bv.z; o[0][3] += a0 * bv.w;
            o[1][0] += a1 * bv.x; o[1][1] += a1 * bv.y; o[1][2] += a1 * bv.z; o[1][3] += a1 * bv.w;
            o[2][0] += a2 * bv.x; o[2][1] += a2 * bv.y; o[2][2] += a2 * bv.z; o[2][3] += a2 * bv.w;
            o[3][0] += a3 * bv.x; o[3][1] += a3 * bv.y; o[3][2] += a3 * bv.z; o[3][3] += a3 * bv.w;
        }
    }

    // ---- write O tile to merged [b, s, h*D] layout
    float* Ob = O + ((size_t)(b * SEQ + q0 + (ty << 2)) * DMODEL) + h * DEPTH + (tx << 2);
    #pragma unroll
    for (int i = 0; i < 4; i++) {
        float4 v = make_float4(o[i][0], o[i][1], o[i][2], o[i][3]);
        *(float4*)(Ob + (size_t)i * DMODEL) = v;
    }
}

// ---------------------------------------------------------------------------
extern "C" void kernel_launch(void* const* d_in, const int* in_sizes, int n_in,
                              void* d_out, int out_size) {
    const float* x  = (const float*)d_in[0];
    const float* Wq = (const float*)d_in[1];
    const float* Wk = (const float*)d_in[2];
    const float* Wv = (const float*)d_in[3];
    const float* Wo = (const float*)d_in[4];
    float* out = (float*)d_out;

    float *Qp, *Kp, *Vp, *Ap;
    cudaGetSymbolAddress((void**)&Qp, g_Q);
    cudaGetSymbolAddress((void**)&Kp, g_K);
    cudaGetSymbolAddress((void**)&Vp, g_V);
    cudaGetSymbolAddress((void**)&Ap, g_A);

    dim3 tb(16, 16);
    dim3 gg(DMODEL / 64, MROWS / 64);          // (8, 128)
    dim3 ga(SEQ / 64, HEADS, BATCH);           // (32, 8, 4)

    gemm_xwt_kernel<<<gg, tb>>>(x, Wq, Qp);
    gemm_xwt_kernel<<<gg, tb>>>(x, Wk, Kp);
    gemm_xwt_kernel<<<gg, tb>>>(x, Wv, Vp);
    attn_kernel<<<ga, tb>>>(Qp, Kp, Vp, Ap);
    gemm_xwt_kernel<<<gg, tb>>>(Ap, Wo, out);
}

// round 5
// speedup vs baseline: 3.0352x; 3.0263x over previous
#include <cuda_runtime.h>
#include <cstdint>
#include <math.h>

#define BATCH  4
#define SEQ    2048
#define HEADS  8
#define DEPTH  64
#define DMODEL 512
#define MROWS  (BATCH*SEQ)   // 8192

__device__ float g_Q[MROWS * DMODEL];
__device__ float g_K[MROWS * DMODEL];
__device__ float g_V[MROWS * DMODEL];
__device__ float g_A[MROWS * DMODEL];

// float -> tf32 bits (round-to-nearest-a)
__device__ __forceinline__ uint32_t f2tf(float x) {
    float r; asm("cvt.rna.tf32.f32 %0, %1;" : "=f"(r) : "f"(x));
    return __float_as_uint(r);
}
// D += A*B  (m16n8k8 tf32, fp32 accum, in-place)
__device__ __forceinline__ void mma8(float* d, const uint32_t* a, const uint32_t* b) {
    asm volatile(
        "mma.sync.aligned.m16n8k8.row.col.f32.tf32.tf32.f32 "
        "{%0,%1,%2,%3}, {%4,%5,%6,%7}, {%8,%9}, {%0,%1,%2,%3};"
        : "+f"(d[0]), "+f"(d[1]), "+f"(d[2]), "+f"(d[3])
        : "r"(a[0]), "r"(a[1]), "r"(a[2]), "r"(a[3]), "r"(b[0]), "r"(b[1]));
}
__device__ __forceinline__ float ex2f(float x) {
    float r; asm("ex2.approx.f32 %0, %1;" : "=f"(r) : "f"(x));
    return r;
}

// ---------------------------------------------------------------------------
// GEMM: out[m][n] = sum_k A[m][k] * W[n][k]   (tf32 mma.sync)
// CTA tile 128x128, 8 warps (2M x 4N), warp tile 64x32, BK=32.
// Smem stride 36 floats (36%32==4): fragment banks = (4*group+thread) -> CF.
// ---------------------------------------------------------------------------
__global__ __launch_bounds__(256) void gemm_tc(
    const float* __restrict__ A, const float* __restrict__ W,
    float* __restrict__ out)
{
    __shared__ uint32_t As[128 * 36];
    __shared__ uint32_t Ws[128 * 36];

    const int tid = threadIdx.x, wid = tid >> 5, lane = tid & 31;
    const int g = lane >> 2, t = lane & 3;
    const int wm = wid & 1, wn = wid >> 1;
    const int m0 = blockIdx.y * 128, n0 = blockIdx.x * 128;

    float acc[4][4][4] = {};

    for (int kc = 0; kc < 16; kc++) {
        const int k0 = kc * 32;
        float4 va[4], vw[4];
        #pragma unroll
        for (int j = 0; j < 4; j++) {
            int idx = tid + 256 * j, r = idx >> 3, c = (idx & 7) << 2;
            va[j] = *(const float4*)(A + (size_t)(m0 + r) * DMODEL + k0 + c);
            vw[j] = *(const float4*)(W + (size_t)(n0 + r) * DMODEL + k0 + c);
        }
        __syncthreads();   // previous chunk's mma reads done
        #pragma unroll
        for (int j = 0; j < 4; j++) {
            int idx = tid + 256 * j, r = idx >> 3, c = (idx & 7) << 2;
            uint32_t* pa = As + r * 36 + c;
            pa[0] = f2tf(va[j].x); pa[1] = f2tf(va[j].y);
            pa[2] = f2tf(va[j].z); pa[3] = f2tf(va[j].w);
            uint32_t* pw = Ws + r * 36 + c;
            pw[0] = f2tf(vw[j].x); pw[1] = f2tf(vw[j].y);
            pw[2] = f2tf(vw[j].z); pw[3] = f2tf(vw[j].w);
        }
        __syncthreads();

        #pragma unroll
        for (int kk = 0; kk < 4; kk++) {
            uint32_t af[4][4], bf[4][2];
            #pragma unroll
            for (int mi = 0; mi < 4; mi++) {
                int row = wm * 64 + mi * 16 + g, col = kk * 8 + t;
                af[mi][0] = As[row * 36 + col];
                af[mi][1] = As[(row + 8) * 36 + col];
                af[mi][2] = As[row * 36 + col + 4];
                af[mi][3] = As[(row + 8) * 36 + col + 4];
            }
            #pragma unroll
            for (int ni = 0; ni < 4; ni++) {
                int rn = wn * 32 + ni * 8 + g, col = kk * 8 + t;
                bf[ni][0] = Ws[rn * 36 + col];
                bf[ni][1] = Ws[rn * 36 + col + 4];
            }
            #pragma unroll
            for (int mi = 0; mi < 4; mi++)
                #pragma unroll
                for (int ni = 0; ni < 4; ni++)
                    mma8(acc[mi][ni], af[mi], bf[ni]);
        }
    }

    #pragma unroll
    for (int mi = 0; mi < 4; mi++) {
        #pragma unroll
        for (int ni = 0; ni < 4; ni++) {
            int r = m0 + wm * 64 + mi * 16 + g;
            int c = n0 + wn * 32 + ni * 8 + 2 * t;
            *(float2*)(out + (size_t)r * DMODEL + c) =
                make_float2(acc[mi][ni][0], acc[mi][ni][1]);
            *(float2*)(out + (size_t)(r + 8) * DMODEL + c) =
                make_float2(acc[mi][ni][2], acc[mi][ni][3]);
        }
    }
}

// ---------------------------------------------------------------------------
// Attention (tf32 mma.sync): CTA = (b, h, 128 queries); 16 key tiles of 128.
// S = Q K^T (regs) -> sigmoid poly -> P (tf32 smem) -> O += P V (regs).
// Warp grid 2M x 4N. S warp tile 64x32; PV warp tile 64x16.
// Smem: Q[128][68] K[128][68] V[128][72] P[128][132]  = 174080 B dynamic.
// ---------------------------------------------------------------------------
__global__ __launch_bounds__(256) void attn_tc(
    const float* __restrict__ Q, const float* __restrict__ K,
    const float* __restrict__ V, float* __restrict__ O)
{
    extern __shared__ char sm[];
    uint32_t* Qs = (uint32_t*)sm;              // 128 x 68
    uint32_t* Ks = (uint32_t*)(sm + 34816);    // 128 x 68
    uint32_t* Vs = (uint32_t*)(sm + 69632);    // 128 x 72
    uint32_t* Ps = (uint32_t*)(sm + 106496);   // 128 x 132

    const int tid = threadIdx.x, wid = tid >> 5, lane = tid & 31;
    const int g = lane >> 2, t = lane & 3;
    const int wm = wid & 1, wn = wid >> 1;
    const int q0 = blockIdx.x * 128, h = blockIdx.y, b = blockIdx.z;

    const float* Qg = Q + (size_t)(b * SEQ + q0) * DMODEL + h * DEPTH;
    const float* Kg = K + (size_t)(b * SEQ) * DMODEL + h * DEPTH;
    const float* Vg = V + (size_t)(b * SEQ) * DMODEL + h * DEPTH;

    // Q tile -> smem (tf32)
    #pragma unroll
    for (int j = 0; j < 8; j++) {
        int idx = tid + 256 * j, r = idx >> 4, c = (idx & 15) << 2;
        float4 v = *(const float4*)(Qg + (size_t)r * DMODEL + c);
        uint32_t* p = Qs + r * 68 + c;
        p[0] = f2tf(v.x); p[1] = f2tf(v.y); p[2] = f2tf(v.z); p[3] = f2tf(v.w);
    }

    float o[4][2][4] = {};
    const float C1 = 0.18033688f;   // 0.125 * log2(e);  bias*log2e = -11 exactly

    for (int kt = 0; kt < 16; kt++) {
        float4 vk[8], vv[8];
        #pragma unroll
        for (int j = 0; j < 8; j++) {
            int idx = tid + 256 * j, r = idx >> 4, c = (idx & 15) << 2;
            vk[j] = *(const float4*)(Kg + (size_t)(kt * 128 + r) * DMODEL + c);
            vv[j] = *(const float4*)(Vg + (size_t)(kt * 128 + r) * DMODEL + c);
        }
        __syncthreads();   // prev iter's PV reads of V/P done (Q stores done, iter0)
        #pragma unroll
        for (int j = 0; j < 8; j++) {
            int idx = tid + 256 * j, r = idx >> 4, c = (idx & 15) << 2;
            uint32_t* pk = Ks + r * 68 + c;
            pk[0] = f2tf(vk[j].x); pk[1] = f2tf(vk[j].y);
            pk[2] = f2tf(vk[j].z); pk[3] = f2tf(vk[j].w);
            uint32_t* pv = Vs + r * 72 + c;
            pv[0] = f2tf(vv[j].x); pv[1] = f2tf(vv[j].y);
            pv[2] = f2tf(vv[j].z); pv[3] = f2tf(vv[j].w);
        }
        __syncthreads();

        // ---- S = Q K^T : warp tile 64x32, 8 k-steps over depth 64
        float s[4][4][4] = {};
        #pragma unroll
        for (int kk = 0; kk < 8; kk++) {
            uint32_t af[4][4], bf[4][2];
            #pragma unroll
            for (int mi = 0; mi < 4; mi++) {
                int row = wm * 64 + mi * 16 + g, col = kk * 8 + t;
                af[mi][0] = Qs[row * 68 + col];
                af[mi][1] = Qs[(row + 8) * 68 + col];
                af[mi][2] = Qs[row * 68 + col + 4];
                af[mi][3] = Qs[(row + 8) * 68 + col + 4];
            }
            #pragma unroll
            for (int ni = 0; ni < 4; ni++) {
                int rn = wn * 32 + ni * 8 + g, col = kk * 8 + t;
                bf[ni][0] = Ks[rn * 68 + col];
                bf[ni][1] = Ks[rn * 68 + col + 4];
            }
            #pragma unroll
            for (int mi = 0; mi < 4; mi++)
                #pragma unroll
                for (int ni = 0; ni < 4; ni++)
                    mma8(s[mi][ni], af[mi], bf[ni]);
        }

        // ---- P = sigmoid(s/8 - log 2048):  y = 2^(s*C1 - 11);  1/(1+y) poly
        #pragma unroll
        for (int mi = 0; mi < 4; mi++) {
            #pragma unroll
            for (int ni = 0; ni < 4; ni++) {
                uint32_t pt[4];
                #pragma unroll
                for (int e = 0; e < 4; e++) {
                    float y = ex2f(s[mi][ni][e] * C1 - 11.0f);
                    float y2 = y * y;
                    float p = y * (1.0f - y) * (1.0f + y2) * (1.0f + y2 * y2);
                    pt[e] = f2tf(p);
                }
                int r = wm * 64 + mi * 16 + g;
                int c = wn * 32 + ni * 8 + 2 * t;
                *(uint2*)(Ps + r * 132 + c)       = make_uint2(pt[0], pt[1]);
                *(uint2*)(Ps + (r + 8) * 132 + c) = make_uint2(pt[2], pt[3]);
            }
        }
        __syncthreads();

        // ---- O += P V : warp tile 64x16, 16 k-steps over 128 keys
        #pragma unroll
        for (int kk = 0; kk < 16; kk++) {
            uint32_t af[4][4], bf[2][2];
            #pragma unroll
            for (int mi = 0; mi < 4; mi++) {
                int row = wm * 64 + mi * 16 + g, col = kk * 8 + t;
                af[mi][0] = Ps[row * 132 + col];
                af[mi][1] = Ps[(row + 8) * 132 + col];
                af[mi][2] = Ps[row * 132 + col + 4];
                af[mi][3] = Ps[(row + 8) * 132 + col + 4];
            }
            #pragma unroll
            for (int ni = 0; ni < 2; ni++) {
                int d = wn * 16 + ni * 8 + g;
                bf[ni][0] = Vs[(kk * 8 + t) * 72 + d];
                bf[ni][1] = Vs[(kk * 8 + t + 4) * 72 + d];
            }
            #pragma unroll
            for (int mi = 0; mi < 4; mi++)
                #pragma unroll
                for (int ni = 0; ni < 2; ni++)
                    mma8(o[mi][ni], af[mi], bf[ni]);
        }
    }

    // ---- write O tile
    float* Og = O + (size_t)(b * SEQ + q0) * DMODEL + h * DEPTH;
    #pragma unroll
    for (int mi = 0; mi < 4; mi++) {
        #pragma unroll
        for (int ni = 0; ni < 2; ni++) {
            int r = wm * 64 + mi * 16 + g;
            int c = wn * 16 + ni * 8 + 2 * t;
            *(float2*)(Og + (size_t)r * DMODEL + c) =
                make_float2(o[mi][ni][0], o[mi][ni][1]);
            *(float2*)(Og + (size_t)(r + 8) * DMODEL + c) =
                make_float2(o[mi][ni][2], o[mi][ni][3]);
        }
    }
}

// ---------------------------------------------------------------------------
extern "C" void kernel_launch(void* const* d_in, const int* in_sizes, int n_in,
                              void* d_out, int out_size) {
    const float* x  = (const float*)d_in[0];
    const float* Wq = (const float*)d_in[1];
    const float* Wk = (const float*)d_in[2];
    const float* Wv = (const float*)d_in[3];
    const float* Wo = (const float*)d_in[4];
    float* out = (float*)d_out;

    float *Qp, *Kp, *Vp, *Ap;
    cudaGetSymbolAddress((void**)&Qp, g_Q);
    cudaGetSymbolAddress((void**)&Kp, g_K);
    cudaGetSymbolAddress((void**)&Vp, g_V);
    cudaGetSymbolAddress((void**)&Ap, g_A);

    const int ATTN_SMEM = 174080;
    static int attr_done = 0;
    cudaFuncSetAttribute(attn_tc, cudaFuncAttributeMaxDynamicSharedMemorySize, ATTN_SMEM);
    (void)attr_done;

    dim3 gg(DMODEL / 128, MROWS / 128);   // (4, 64)
    dim3 ga(SEQ / 128, HEADS, BATCH);     // (16, 8, 4)

    gemm_tc<<<gg, 256>>>(x, Wq, Qp);
    gemm_tc<<<gg, 256>>>(x, Wk, Kp);
    gemm_tc<<<gg, 256>>>(x, Wv, Vp);
    attn_tc<<<ga, 256, ATTN_SMEM>>>(Qp, Kp, Vp, Ap);
    gemm_tc<<<gg, 256>>>(Ap, Wo, out);
}